// round 6
// baseline (speedup 1.0000x reference)
#include <cuda_runtime.h>
#include <cuda_fp16.h>
#include <cstdint>

#define N_FEAT 32
#define N_COLS 128          // 4 relations * 32 output features
#define MAX_NODES 524288
#define MAX_EDGES 4194304
#define TN 128              // nodes per transform block

#define XH_STRIDE 40        // halfs per x-tile row (padded, conflict-free ldmatrix)
#define WH_STRIDE 136       // halfs per W row (padded)
#define ST_STRIDE 136       // halfs per staging row

// Scratch: xt fp16 (128 MB), agg fp32 (64 MB x2), CSR arrays.
__device__ __half g_xt[(size_t)MAX_NODES * N_COLS];
__device__ float  g_agg1[(size_t)MAX_NODES * N_FEAT];
__device__ float  g_agg2[(size_t)MAX_NODES * N_FEAT];
__device__ unsigned int g_perm[MAX_EDGES];      // (src<<2)|rel, dst-sorted
__device__ int g_rowptr[MAX_NODES + 1];
__device__ int g_cnt[MAX_NODES];                // counts, then cursor
__device__ int g_bsum[512];

// ---------------------------------------------------------------------------
// CSR build: zero counts -> histogram -> 3-phase scan -> reorder.
// ---------------------------------------------------------------------------
__global__ void zero_cnt_k(int* __restrict__ cnt, int n)
{
    const int i = blockIdx.x * blockDim.x + threadIdx.x;
    if (i < n) cnt[i] = 0;
}

__global__ void hist_k(const int* __restrict__ dst, int* __restrict__ cnt, int ne)
{
    const int e = blockIdx.x * blockDim.x + threadIdx.x;
    if (e < ne) atomicAdd(&cnt[__ldg(dst + e)], 1);
}

// 512 blocks x 1024 elements (256 threads x int4). Exclusive scan per block.
__global__ void __launch_bounds__(256) scan1_k(
    const int* __restrict__ cnt, int* __restrict__ out, int* __restrict__ bsum)
{
    __shared__ int s[256];
    const int tid = threadIdx.x;
    const int idx = blockIdx.x * 1024 + tid * 4;

    const int4 c = *reinterpret_cast<const int4*>(cnt + idx);
    const int tsum = c.x + c.y + c.z + c.w;

    s[tid] = tsum;
    __syncthreads();
    #pragma unroll
    for (int off = 1; off < 256; off <<= 1) {
        const int v = (tid >= off) ? s[tid - off] : 0;
        __syncthreads();
        s[tid] += v;
        __syncthreads();
    }
    const int excl = s[tid] - tsum;

    int4 o;
    o.x = excl;
    o.y = o.x + c.x;
    o.z = o.y + c.y;
    o.w = o.z + c.z;
    *reinterpret_cast<int4*>(out + idx) = o;

    if (tid == 255) bsum[blockIdx.x] = s[255];
}

// Single block: exclusive scan of 512 block sums in place.
__global__ void __launch_bounds__(512) scan2_k(int* __restrict__ bsum)
{
    __shared__ int s[512];
    const int tid = threadIdx.x;
    const int v0 = bsum[tid];
    s[tid] = v0;
    __syncthreads();
    #pragma unroll
    for (int off = 1; off < 512; off <<= 1) {
        const int v = (tid >= off) ? s[tid - off] : 0;
        __syncthreads();
        s[tid] += v;
        __syncthreads();
    }
    bsum[tid] = s[tid] - v0;   // exclusive
}

// Add block offsets; produce final rowptr and cursor copy.
__global__ void __launch_bounds__(256) scan3_k(
    int* __restrict__ rowptr, int* __restrict__ cursor,
    const int* __restrict__ bsum, int nnodes, int ne)
{
    const int idx = blockIdx.x * 1024 + threadIdx.x * 4;
    const int boff = bsum[blockIdx.x];
    int4 v = *reinterpret_cast<int4*>(rowptr + idx);
    v.x += boff; v.y += boff; v.z += boff; v.w += boff;
    *reinterpret_cast<int4*>(rowptr + idx) = v;
    *reinterpret_cast<int4*>(cursor + idx) = v;
    if (blockIdx.x == 0 && threadIdx.x == 0) rowptr[nnodes] = ne;
}

__global__ void reorder_k(
    const int* __restrict__ src, const int* __restrict__ dst,
    const int* __restrict__ et, int* __restrict__ cursor,
    unsigned int* __restrict__ perm, int ne)
{
    const int e = blockIdx.x * blockDim.x + threadIdx.x;
    if (e >= ne) return;
    const int d = __ldg(dst + e);
    const unsigned int p = ((unsigned int)__ldg(src + e) << 2) | (unsigned int)__ldg(et + e);
    const int pos = atomicAdd(&cursor[d], 1);
    perm[pos] = p;
}

// ---------------------------------------------------------------------------
// Aggregation: one warp per node, lane = feature. fp32 register accumulate,
// no atomics. agg[n][lane] = sum_{e in rowptr[n]..rowptr[n+1]} xt[perm[e]*32+lane]
// (perm[e]*32 + lane == src*128 + rel*32 + lane: the needed xt slice.)
// ---------------------------------------------------------------------------
__global__ void __launch_bounds__(256) agg_k(
    const __half* __restrict__ xt, const unsigned int* __restrict__ perm,
    const int* __restrict__ rowptr, float* __restrict__ agg, int nnodes)
{
    const int wid  = (blockIdx.x * blockDim.x + threadIdx.x) >> 5;
    const int lane = threadIdx.x & 31;
    if (wid >= nnodes) return;

    const int e0 = __ldg(rowptr + wid);
    const int e1 = __ldg(rowptr + wid + 1);

    float acc = 0.f;
    for (int eb = e0; eb < e1; eb += 32) {
        const int cnt = min(32, e1 - eb);
        const unsigned int pl = (eb + lane < e1) ? __ldg(perm + eb + lane) : 0u;
        for (int i = 0; i < cnt; i++) {
            const unsigned int p = __shfl_sync(0xffffffffu, pl, i);
            acc += __half2float(__ldg(xt + ((size_t)p << 5) + lane));
        }
    }
    agg[(size_t)wid * N_FEAT + lane] = acc;
}

// ---------------------------------------------------------------------------
// Tensor-core transform: xt[n][r*32+o] = sum_d act(in[n][d])*W[r][d][o]
// PRE_ACT: in is fp32 agg, apply relu(v + b[d]). Else: in is fp32 x.
// ---------------------------------------------------------------------------
template<bool PRE_ACT>
__global__ void __launch_bounds__(256) transform_k(
    const float* __restrict__ xin, const float* __restrict__ W,
    const float* __restrict__ b, __half* __restrict__ xt)
{
    __shared__ __align__(16) unsigned char sm[TN * ST_STRIDE * 2]; // 34816 B
    __half* xh    = reinterpret_cast<__half*>(sm);           // [128][XH_STRIDE]
    __half* wh    = reinterpret_cast<__half*>(sm + 10240);   // [32][WH_STRIDE]
    __half* stage = reinterpret_cast<__half*>(sm);           // [128][ST_STRIDE]

    const int tid  = threadIdx.x;
    const int base = blockIdx.x * TN;

    // Fill W smem: wh[d][r*32+o] = half(W[r][d][o]).
    for (int f = tid; f < 1024; f += 256) {
        const float4 v = reinterpret_cast<const float4*>(W)[f];
        const int r = f >> 8, d = (f >> 3) & 31, o4 = f & 7;
        __half* p = &wh[d * WH_STRIDE + r * 32 + o4 * 4];
        p[0] = __float2half_rn(v.x); p[1] = __float2half_rn(v.y);
        p[2] = __float2half_rn(v.z); p[3] = __float2half_rn(v.w);
    }

    // Fill x tile (fp32 in, fp16 out; bias+relu for layer-2 input).
    const float4* xin4 = reinterpret_cast<const float4*>(xin + (size_t)base * N_FEAT);
    for (int f = tid; f < TN * 8; f += 256) {
        float4 v = xin4[f];
        const int i = f >> 3, kq = f & 7;
        if (PRE_ACT) {
            v.x = fmaxf(v.x + __ldg(b + kq * 4 + 0), 0.f);
            v.y = fmaxf(v.y + __ldg(b + kq * 4 + 1), 0.f);
            v.z = fmaxf(v.z + __ldg(b + kq * 4 + 2), 0.f);
            v.w = fmaxf(v.w + __ldg(b + kq * 4 + 3), 0.f);
        }
        __half* d = &xh[i * XH_STRIDE + kq * 4];
        *reinterpret_cast<__half2*>(d)     = __floats2half2_rn(v.x, v.y);
        *reinterpret_cast<__half2*>(d + 2) = __floats2half2_rn(v.z, v.w);
    }
    __syncthreads();

    const int w    = tid >> 5;
    const int lane = tid & 31;
    const int m0   = w * 16;

    uint32_t a[2][4];
    #pragma unroll
    for (int s = 0; s < 2; s++) {
        const int row = m0 + (lane & 15);
        const int col = s * 16 + ((lane >> 4) << 3);
        const uint32_t addr =
            (uint32_t)__cvta_generic_to_shared(&xh[row * XH_STRIDE + col]);
        asm volatile("ldmatrix.sync.aligned.m8n8.x4.shared.b16 {%0,%1,%2,%3}, [%4];"
                     : "=r"(a[s][0]), "=r"(a[s][1]), "=r"(a[s][2]), "=r"(a[s][3])
                     : "r"(addr));
    }

    float acc[16][4];
    #pragma unroll
    for (int j = 0; j < 16; j++)
        #pragma unroll
        for (int q = 0; q < 4; q++) acc[j][q] = 0.f;

    #pragma unroll
    for (int j = 0; j < 16; j++) {
        #pragma unroll
        for (int s = 0; s < 2; s++) {
            const int krow = s * 16 + (lane & 15);
            const uint32_t baddr =
                (uint32_t)__cvta_generic_to_shared(&wh[krow * WH_STRIDE + j * 8]);
            uint32_t b0, b1;
            asm volatile("ldmatrix.sync.aligned.m8n8.x2.trans.shared.b16 {%0,%1}, [%2];"
                         : "=r"(b0), "=r"(b1) : "r"(baddr));
            asm volatile(
                "mma.sync.aligned.m16n8k16.row.col.f32.f16.f16.f32 "
                "{%0,%1,%2,%3}, {%4,%5,%6,%7}, {%8,%9}, {%0,%1,%2,%3};"
                : "+f"(acc[j][0]), "+f"(acc[j][1]), "+f"(acc[j][2]), "+f"(acc[j][3])
                : "r"(a[s][0]), "r"(a[s][1]), "r"(a[s][2]), "r"(a[s][3]),
                  "r"(b0), "r"(b1));
        }
    }
    __syncthreads();   // xh/wh dead; reuse as staging

    const int g  = lane >> 2;
    const int t4 = lane & 3;
    #pragma unroll
    for (int j = 0; j < 16; j++) {
        *reinterpret_cast<__half2*>(&stage[(m0 + g) * ST_STRIDE + j * 8 + t4 * 2]) =
            __floats2half2_rn(acc[j][0], acc[j][1]);
        *reinterpret_cast<__half2*>(&stage[(m0 + g + 8) * ST_STRIDE + j * 8 + t4 * 2]) =
            __floats2half2_rn(acc[j][2], acc[j][3]);
    }
    __syncthreads();

    for (int f = tid; f < TN * 16; f += 256) {
        const int row = f >> 4, ch = f & 15;
        const uint4 v = *reinterpret_cast<const uint4*>(&stage[row * ST_STRIDE + ch * 8]);
        *reinterpret_cast<uint4*>(xt + (size_t)(base + row) * N_COLS + ch * 8) = v;
    }
}

// ---------------------------------------------------------------------------
// Pool: out[g][c] = mean_{i<32} relu(agg2[g*32+i][c] + b[c]).
// ---------------------------------------------------------------------------
__global__ void __launch_bounds__(256) pool_k(
    const float* __restrict__ agg, const float* __restrict__ b,
    float* __restrict__ out, int nnodes)
{
    const int t = blockIdx.x * blockDim.x + threadIdx.x;
    if (t >= nnodes) return;
    const int c = t & 31;
    const int g = t >> 5;
    const float bc = __ldg(b + c);
    const float* p = agg + (size_t)g * 32 * N_FEAT + c;
    float s = 0.f;
    #pragma unroll
    for (int i = 0; i < 32; i++)
        s += fmaxf(p[i * N_FEAT] + bc, 0.f);
    out[t] = s * (1.0f / 32.0f);
}

// ---------------------------------------------------------------------------
extern "C" void kernel_launch(void* const* d_in, const int* in_sizes, int n_in,
                              void* d_out, int out_size)
{
    const float* x   = (const float*)d_in[0];
    const int*   src = (const int*)  d_in[1];
    const int*   dst = (const int*)  d_in[2];
    const int*   et  = (const int*)  d_in[3];
    const float* W   = (const float*)d_in[4];
    const float* b   = (const float*)d_in[5];

    const int nnodes = in_sizes[0] / N_FEAT;
    const int nedges = in_sizes[1];

    __half *xt; float *agg1, *agg2;
    unsigned int *perm; int *rowptr, *cnt, *bsum;
    cudaGetSymbolAddress((void**)&xt,     g_xt);
    cudaGetSymbolAddress((void**)&agg1,   g_agg1);
    cudaGetSymbolAddress((void**)&agg2,   g_agg2);
    cudaGetSymbolAddress((void**)&perm,   g_perm);
    cudaGetSymbolAddress((void**)&rowptr, g_rowptr);
    cudaGetSymbolAddress((void**)&cnt,    g_cnt);
    cudaGetSymbolAddress((void**)&bsum,   g_bsum);

    const int tf_blocks = nnodes / TN;
    const int eb_blocks = (nedges + 255) / 256;
    const int scan_blks = nnodes / 1024;               // 512 for N=524288
    const int ag_blocks = (nnodes * 32 + 255) / 256;   // warp per node

    // ---- Build dst-CSR once (shared by both layers) ----
    zero_cnt_k<<<(nnodes + 255) / 256, 256>>>(cnt, nnodes);
    hist_k<<<eb_blocks, 256>>>(dst, cnt, nedges);
    scan1_k<<<scan_blks, 256>>>(cnt, rowptr, bsum);
    scan2_k<<<1, 512>>>(bsum);
    scan3_k<<<scan_blks, 256>>>(rowptr, cnt, bsum, nnodes, nedges);
    reorder_k<<<eb_blocks, 256>>>(src, dst, et, cnt, perm, nedges);

    // ---- Layer 1 ----
    transform_k<false><<<tf_blocks, 256>>>(x, W, b, xt);
    agg_k<<<ag_blocks, 256>>>(xt, perm, rowptr, agg1, nnodes);

    // ---- Layer 2 (input = relu(agg1 + b), fused into transform) ----
    transform_k<true><<<tf_blocks, 256>>>(agg1, W, b, xt);
    agg_k<<<ag_blocks, 256>>>(xt, perm, rowptr, agg2, nnodes);

    // ---- Pool (bias+relu fused) ----
    pool_k<<<(nnodes + 255) / 256, 256>>>(agg2, b, (float*)d_out, nnodes);
    (void)n_in; (void)out_size;
}

// round 7
// speedup vs baseline: 1.2096x; 1.2096x over previous
#include <cuda_runtime.h>
#include <cuda_fp16.h>
#include <cstdint>

#define N_FEAT 32
#define N_COLS 128          // 4 relations * 32 output features
#define MAX_NODES 524288
#define MAX_EDGES 4194304
#define TN 128              // nodes per transform block

#define XH_STRIDE 40        // halfs per x-tile row (padded, conflict-free ldmatrix)
#define WH_STRIDE 136       // halfs per W row (padded)
#define ST_STRIDE 136       // halfs per staging row

// Scratch: xt fp16 (128 MB), agg fp32 (64 MB x2), CSR arrays.
__device__ __half g_xt[(size_t)MAX_NODES * N_COLS];
__device__ float  g_agg1[(size_t)MAX_NODES * N_FEAT];
__device__ float  g_agg2[(size_t)MAX_NODES * N_FEAT];
__device__ unsigned int g_perm[MAX_EDGES];      // (src<<2)|rel, dst-sorted
__device__ int g_rowptr[MAX_NODES + 1];
__device__ int g_cnt[MAX_NODES];                // counts, then cursor
__device__ int g_bsum[512];

// ---------------------------------------------------------------------------
// CSR build: zero counts -> histogram -> 3-phase scan -> reorder.
// ---------------------------------------------------------------------------
__global__ void zero_cnt_k(int* __restrict__ cnt, int n)
{
    const int i = blockIdx.x * blockDim.x + threadIdx.x;
    if (i < n) cnt[i] = 0;
}

__global__ void hist_k(const int* __restrict__ dst, int* __restrict__ cnt, int ne)
{
    const int e = blockIdx.x * blockDim.x + threadIdx.x;
    if (e < ne) atomicAdd(&cnt[__ldg(dst + e)], 1);
}

// 512 blocks x 1024 elements (256 threads x int4). Exclusive scan per block.
__global__ void __launch_bounds__(256) scan1_k(
    const int* __restrict__ cnt, int* __restrict__ out, int* __restrict__ bsum)
{
    __shared__ int s[256];
    const int tid = threadIdx.x;
    const int idx = blockIdx.x * 1024 + tid * 4;

    const int4 c = *reinterpret_cast<const int4*>(cnt + idx);
    const int tsum = c.x + c.y + c.z + c.w;

    s[tid] = tsum;
    __syncthreads();
    #pragma unroll
    for (int off = 1; off < 256; off <<= 1) {
        const int v = (tid >= off) ? s[tid - off] : 0;
        __syncthreads();
        s[tid] += v;
        __syncthreads();
    }
    const int excl = s[tid] - tsum;

    int4 o;
    o.x = excl;
    o.y = o.x + c.x;
    o.z = o.y + c.y;
    o.w = o.z + c.z;
    *reinterpret_cast<int4*>(out + idx) = o;

    if (tid == 255) bsum[blockIdx.x] = s[255];
}

// Single block: exclusive scan of 512 block sums in place.
__global__ void __launch_bounds__(512) scan2_k(int* __restrict__ bsum)
{
    __shared__ int s[512];
    const int tid = threadIdx.x;
    const int v0 = bsum[tid];
    s[tid] = v0;
    __syncthreads();
    #pragma unroll
    for (int off = 1; off < 512; off <<= 1) {
        const int v = (tid >= off) ? s[tid - off] : 0;
        __syncthreads();
        s[tid] += v;
        __syncthreads();
    }
    bsum[tid] = s[tid] - v0;   // exclusive
}

// Add block offsets; produce final rowptr and cursor copy.
__global__ void __launch_bounds__(256) scan3_k(
    int* __restrict__ rowptr, int* __restrict__ cursor,
    const int* __restrict__ bsum, int nnodes, int ne)
{
    const int idx = blockIdx.x * 1024 + threadIdx.x * 4;
    const int boff = bsum[blockIdx.x];
    int4 v = *reinterpret_cast<int4*>(rowptr + idx);
    v.x += boff; v.y += boff; v.z += boff; v.w += boff;
    *reinterpret_cast<int4*>(rowptr + idx) = v;
    *reinterpret_cast<int4*>(cursor + idx) = v;
    if (blockIdx.x == 0 && threadIdx.x == 0) rowptr[nnodes] = ne;
}

__global__ void reorder_k(
    const int* __restrict__ src, const int* __restrict__ dst,
    const int* __restrict__ et, int* __restrict__ cursor,
    unsigned int* __restrict__ perm, int ne)
{
    const int e = blockIdx.x * blockDim.x + threadIdx.x;
    if (e >= ne) return;
    const int d = __ldg(dst + e);
    const unsigned int p = ((unsigned int)__ldg(src + e) << 2) | (unsigned int)__ldg(et + e);
    const int pos = atomicAdd(&cursor[d], 1);
    perm[pos] = p;
}

// ---------------------------------------------------------------------------
// Aggregation: one warp per node, lane = feature. fp32 register accumulate,
// no atomics. agg[n][lane] = sum_e xt[perm[e]*32 + lane].
// MLP fix vs R6: broadcast 8 perm values, then issue 8 predicated unrolled
// gathers back-to-back (8 loads in flight per warp step, no serial
// shfl->ldg->fadd interleave, no dynamic-bound inner loop).
// ---------------------------------------------------------------------------
__global__ void __launch_bounds__(256) agg_k(
    const __half* __restrict__ xt, const unsigned int* __restrict__ perm,
    const int* __restrict__ rowptr, float* __restrict__ agg, int nnodes)
{
    const int wid  = (blockIdx.x * blockDim.x + threadIdx.x) >> 5;
    const int lane = threadIdx.x & 31;
    if (wid >= nnodes) return;

    const int e0 = __ldg(rowptr + wid);
    const int e1 = __ldg(rowptr + wid + 1);
    const int n  = e1 - e0;

    float acc = 0.f;
    const int n1 = min(n, 32);
    const unsigned int pl = (lane < n1) ? __ldg(perm + e0 + lane) : 0u;

    for (int base = 0; base < n1; base += 8) {
        unsigned int p[8];
        #pragma unroll
        for (int j = 0; j < 8; j++)
            p[j] = __shfl_sync(0xffffffffu, pl, base + j);
        #pragma unroll
        for (int j = 0; j < 8; j++)
            if (base + j < n1)
                acc += __half2float(__ldg(xt + ((size_t)p[j] << 5) + lane));
    }

    // Rare tail: degree > 32 (Poisson(8) tail).
    for (int eb = e0 + 32; eb < e1; eb += 32) {
        const int cnt = min(32, e1 - eb);
        const unsigned int pl2 = (lane < cnt) ? __ldg(perm + eb + lane) : 0u;
        for (int base = 0; base < cnt; base += 8) {
            unsigned int p[8];
            #pragma unroll
            for (int j = 0; j < 8; j++)
                p[j] = __shfl_sync(0xffffffffu, pl2, base + j);
            #pragma unroll
            for (int j = 0; j < 8; j++)
                if (base + j < cnt)
                    acc += __half2float(__ldg(xt + ((size_t)p[j] << 5) + lane));
        }
    }

    agg[(size_t)wid * N_FEAT + lane] = acc;
}

// ---------------------------------------------------------------------------
// Tensor-core transform (unchanged from R4, proven 43.4us):
// xt[n][r*32+o] = sum_d act(in[n][d]) * W[r][d][o]
// PRE_ACT: in is fp32 agg, apply relu(v + b[d]). Else: in is fp32 x.
// ---------------------------------------------------------------------------
template<bool PRE_ACT>
__global__ void __launch_bounds__(256) transform_k(
    const float* __restrict__ xin, const float* __restrict__ W,
    const float* __restrict__ b, __half* __restrict__ xt)
{
    __shared__ __align__(16) unsigned char sm[TN * ST_STRIDE * 2]; // 34816 B
    __half* xh    = reinterpret_cast<__half*>(sm);           // [128][XH_STRIDE]
    __half* wh    = reinterpret_cast<__half*>(sm + 10240);   // [32][WH_STRIDE]
    __half* stage = reinterpret_cast<__half*>(sm);           // [128][ST_STRIDE]

    const int tid  = threadIdx.x;
    const int base = blockIdx.x * TN;

    // Fill W smem: wh[d][r*32+o] = half(W[r][d][o]).
    for (int f = tid; f < 1024; f += 256) {
        const float4 v = reinterpret_cast<const float4*>(W)[f];
        const int r = f >> 8, d = (f >> 3) & 31, o4 = f & 7;
        __half* p = &wh[d * WH_STRIDE + r * 32 + o4 * 4];
        p[0] = __float2half_rn(v.x); p[1] = __float2half_rn(v.y);
        p[2] = __float2half_rn(v.z); p[3] = __float2half_rn(v.w);
    }

    // Fill x tile (fp32 in, fp16 out; bias+relu for layer-2 input).
    const float4* xin4 = reinterpret_cast<const float4*>(xin + (size_t)base * N_FEAT);
    for (int f = tid; f < TN * 8; f += 256) {
        float4 v = xin4[f];
        const int i = f >> 3, kq = f & 7;
        if (PRE_ACT) {
            v.x = fmaxf(v.x + __ldg(b + kq * 4 + 0), 0.f);
            v.y = fmaxf(v.y + __ldg(b + kq * 4 + 1), 0.f);
            v.z = fmaxf(v.z + __ldg(b + kq * 4 + 2), 0.f);
            v.w = fmaxf(v.w + __ldg(b + kq * 4 + 3), 0.f);
        }
        __half* d = &xh[i * XH_STRIDE + kq * 4];
        *reinterpret_cast<__half2*>(d)     = __floats2half2_rn(v.x, v.y);
        *reinterpret_cast<__half2*>(d + 2) = __floats2half2_rn(v.z, v.w);
    }
    __syncthreads();

    const int w    = tid >> 5;
    const int lane = tid & 31;
    const int m0   = w * 16;

    uint32_t a[2][4];
    #pragma unroll
    for (int s = 0; s < 2; s++) {
        const int row = m0 + (lane & 15);
        const int col = s * 16 + ((lane >> 4) << 3);
        const uint32_t addr =
            (uint32_t)__cvta_generic_to_shared(&xh[row * XH_STRIDE + col]);
        asm volatile("ldmatrix.sync.aligned.m8n8.x4.shared.b16 {%0,%1,%2,%3}, [%4];"
                     : "=r"(a[s][0]), "=r"(a[s][1]), "=r"(a[s][2]), "=r"(a[s][3])
                     : "r"(addr));
    }

    float acc[16][4];
    #pragma unroll
    for (int j = 0; j < 16; j++)
        #pragma unroll
        for (int q = 0; q < 4; q++) acc[j][q] = 0.f;

    #pragma unroll
    for (int j = 0; j < 16; j++) {
        #pragma unroll
        for (int s = 0; s < 2; s++) {
            const int krow = s * 16 + (lane & 15);
            const uint32_t baddr =
                (uint32_t)__cvta_generic_to_shared(&wh[krow * WH_STRIDE + j * 8]);
            uint32_t b0, b1;
            asm volatile("ldmatrix.sync.aligned.m8n8.x2.trans.shared.b16 {%0,%1}, [%2];"
                         : "=r"(b0), "=r"(b1) : "r"(baddr));
            asm volatile(
                "mma.sync.aligned.m16n8k16.row.col.f32.f16.f16.f32 "
                "{%0,%1,%2,%3}, {%4,%5,%6,%7}, {%8,%9}, {%0,%1,%2,%3};"
                : "+f"(acc[j][0]), "+f"(acc[j][1]), "+f"(acc[j][2]), "+f"(acc[j][3])
                : "r"(a[s][0]), "r"(a[s][1]), "r"(a[s][2]), "r"(a[s][3]),
                  "r"(b0), "r"(b1));
        }
    }
    __syncthreads();   // xh/wh dead; reuse as staging

    const int g  = lane >> 2;
    const int t4 = lane & 3;
    #pragma unroll
    for (int j = 0; j < 16; j++) {
        *reinterpret_cast<__half2*>(&stage[(m0 + g) * ST_STRIDE + j * 8 + t4 * 2]) =
            __floats2half2_rn(acc[j][0], acc[j][1]);
        *reinterpret_cast<__half2*>(&stage[(m0 + g + 8) * ST_STRIDE + j * 8 + t4 * 2]) =
            __floats2half2_rn(acc[j][2], acc[j][3]);
    }
    __syncthreads();

    for (int f = tid; f < TN * 16; f += 256) {
        const int row = f >> 4, ch = f & 15;
        const uint4 v = *reinterpret_cast<const uint4*>(&stage[row * ST_STRIDE + ch * 8]);
        *reinterpret_cast<uint4*>(xt + (size_t)(base + row) * N_COLS + ch * 8) = v;
    }
}

// ---------------------------------------------------------------------------
// Pool: out[g][c] = mean_{i<32} relu(agg2[g*32+i][c] + b[c]).
// ---------------------------------------------------------------------------
__global__ void __launch_bounds__(256) pool_k(
    const float* __restrict__ agg, const float* __restrict__ b,
    float* __restrict__ out, int nnodes)
{
    const int t = blockIdx.x * blockDim.x + threadIdx.x;
    if (t >= nnodes) return;
    const int c = t & 31;
    const int g = t >> 5;
    const float bc = __ldg(b + c);
    const float* p = agg + (size_t)g * 32 * N_FEAT + c;
    float s = 0.f;
    #pragma unroll
    for (int i = 0; i < 32; i++)
        s += fmaxf(p[i * N_FEAT] + bc, 0.f);
    out[t] = s * (1.0f / 32.0f);
}

// ---------------------------------------------------------------------------
extern "C" void kernel_launch(void* const* d_in, const int* in_sizes, int n_in,
                              void* d_out, int out_size)
{
    const float* x   = (const float*)d_in[0];
    const int*   src = (const int*)  d_in[1];
    const int*   dst = (const int*)  d_in[2];
    const int*   et  = (const int*)  d_in[3];
    const float* W   = (const float*)d_in[4];
    const float* b   = (const float*)d_in[5];

    const int nnodes = in_sizes[0] / N_FEAT;
    const int nedges = in_sizes[1];

    __half *xt; float *agg1, *agg2;
    unsigned int *perm; int *rowptr, *cnt, *bsum;
    cudaGetSymbolAddress((void**)&xt,     g_xt);
    cudaGetSymbolAddress((void**)&agg1,   g_agg1);
    cudaGetSymbolAddress((void**)&agg2,   g_agg2);
    cudaGetSymbolAddress((void**)&perm,   g_perm);
    cudaGetSymbolAddress((void**)&rowptr, g_rowptr);
    cudaGetSymbolAddress((void**)&cnt,    g_cnt);
    cudaGetSymbolAddress((void**)&bsum,   g_bsum);

    const int tf_blocks = nnodes / TN;
    const int eb_blocks = (nedges + 255) / 256;
    const int scan_blks = nnodes / 1024;               // 512 for N=524288
    const int ag_blocks = (nnodes * 32 + 255) / 256;   // warp per node

    // ---- Build dst-CSR once (shared by both layers) ----
    zero_cnt_k<<<(nnodes + 255) / 256, 256>>>(cnt, nnodes);
    hist_k<<<eb_blocks, 256>>>(dst, cnt, nedges);
    scan1_k<<<scan_blks, 256>>>(cnt, rowptr, bsum);
    scan2_k<<<1, 512>>>(bsum);
    scan3_k<<<scan_blks, 256>>>(rowptr, cnt, bsum, nnodes, nedges);
    reorder_k<<<eb_blocks, 256>>>(src, dst, et, cnt, perm, nedges);

    // ---- Layer 1 ----
    transform_k<false><<<tf_blocks, 256>>>(x, W, b, xt);
    agg_k<<<ag_blocks, 256>>>(xt, perm, rowptr, agg1, nnodes);

    // ---- Layer 2 (input = relu(agg1 + b), fused into transform) ----
    transform_k<true><<<tf_blocks, 256>>>(agg1, W, b, xt);
    agg_k<<<ag_blocks, 256>>>(xt, perm, rowptr, agg2, nnodes);

    // ---- Pool (bias+relu fused) ----
    pool_k<<<(nnodes + 255) / 256, 256>>>(agg2, b, (float*)d_out, nnodes);
    (void)n_in; (void)out_size;
}